// round 5
// baseline (speedup 1.0000x reference)
#include <cuda_runtime.h>
#include <cstdint>

// Problem constants (fixed by the dataset)
#define NU 100000
#define NI 50000
#define NT (NU + NI)      // 150000 total nodes
#define D  64             // factors
#define NLAYERS 3

// Static device scratch (allocation is forbidden; 2 x 38.4 MB)
__device__ float g_cur[(size_t)NT * D];
__device__ float g_next[(size_t)NT * D];

// ---------------------------------------------------------------------------
// init: g_cur = concat(user_emb, item_emb); acc (=d_out) = g_cur; g_next = 0
// One thread per float4, grid-stride. NT*D/4 = 2.4M float4s.
// ---------------------------------------------------------------------------
__global__ void lgcn_init(const float* __restrict__ ue,
                          const float* __restrict__ ie,
                          float* __restrict__ acc) {
    const int total4 = NT * D / 4;
    const int user4  = NU * D / 4;
    for (int i = blockIdx.x * blockDim.x + threadIdx.x; i < total4;
         i += gridDim.x * blockDim.x) {
        float4 v;
        if (i < user4) v = reinterpret_cast<const float4*>(ue)[i];
        else           v = reinterpret_cast<const float4*>(ie)[i - user4];
        reinterpret_cast<float4*>(g_cur)[i]  = v;
        reinterpret_cast<float4*>(acc)[i]    = v;
        reinterpret_cast<float4*>(g_next)[i] = make_float4(0.f, 0.f, 0.f, 0.f);
    }
}

// ---------------------------------------------------------------------------
// spmm: for each edge e: next[row[e]] += val[e] * cur[col[e]]
// 16 lanes per edge; each lane handles one float4 (16B) of the 256B row.
// Lane 0 of each 16-lane group loads (row, col, val) once and broadcasts
// via shfl (width=16), cutting index LDG issue 16x.
// Scatter uses vectorized no-return reduction red.global.add.v4.f32.
// ---------------------------------------------------------------------------
__global__ void lgcn_spmm(const int* __restrict__ row,
                          const int* __restrict__ col,
                          const float* __restrict__ val,
                          int nnz) {
    const unsigned FULL = 0xffffffffu;
    long long t0     = (long long)blockIdx.x * blockDim.x + threadIdx.x;
    long long stride = (long long)gridDim.x * blockDim.x;
    long long totalT = (long long)nnz * 16;
    int seg  = (int)(t0 & 15);           // which float4 of the row (invariant: stride%16==0)
    int lead = (seg == 0);

    for (long long t = t0; t < totalT; t += stride) {
        int e = (int)(t >> 4);           // edge id (same for all 16 lanes of group)

        int r = 0, c = 0;
        float v = 0.f;
        if (lead) {                      // one load per edge-group
            r = __ldg(row + e);
            c = __ldg(col + e);
            v = __ldg(val + e);
        }
        r = __shfl_sync(FULL, r, 0, 16);
        c = __shfl_sync(FULL, c, 0, 16);
        v = __shfl_sync(FULL, v, 0, 16);

        const float4* src = reinterpret_cast<const float4*>(g_cur + (size_t)c * D) + seg;
        float4 x = __ldg(src);
        float4 m = make_float4(x.x * v, x.y * v, x.z * v, x.w * v);

        float* dst = g_next + (size_t)r * D + seg * 4;
        asm volatile("red.global.add.v4.f32 [%0], {%1, %2, %3, %4};"
                     :: "l"(dst), "f"(m.x), "f"(m.y), "f"(m.z), "f"(m.w)
                     : "memory");
    }
}

// ---------------------------------------------------------------------------
// combine: acc += next; if not last: cur = next, next = 0; if last: acc *= 0.25
// ---------------------------------------------------------------------------
__global__ void lgcn_combine(float* __restrict__ acc, int last) {
    const int total4 = NT * D / 4;
    for (int i = blockIdx.x * blockDim.x + threadIdx.x; i < total4;
         i += gridDim.x * blockDim.x) {
        float4 n = reinterpret_cast<float4*>(g_next)[i];
        float4 a = reinterpret_cast<float4*>(acc)[i];
        a.x += n.x; a.y += n.y; a.z += n.z; a.w += n.w;
        if (last) {
            a.x *= 0.25f; a.y *= 0.25f; a.z *= 0.25f; a.w *= 0.25f;
            reinterpret_cast<float4*>(acc)[i] = a;
        } else {
            reinterpret_cast<float4*>(acc)[i] = a;
            reinterpret_cast<float4*>(g_cur)[i]  = n;
            reinterpret_cast<float4*>(g_next)[i] = make_float4(0.f, 0.f, 0.f, 0.f);
        }
    }
}

// ---------------------------------------------------------------------------
// launch
// Inputs (metadata order): user_emb f32 [NU*D], item_emb f32 [NI*D],
//                          adj_row i32 [NNZ], adj_col i32 [NNZ], adj_val f32 [NNZ]
// Output: mean_emb f32 [NT*D] (users then items)
// ---------------------------------------------------------------------------
extern "C" void kernel_launch(void* const* d_in, const int* in_sizes, int n_in,
                              void* d_out, int out_size) {
    const float* ue   = (const float*)d_in[0];
    const float* ie   = (const float*)d_in[1];
    const int*   arow = (const int*)d_in[2];
    const int*   acol = (const int*)d_in[3];
    const float* aval = (const float*)d_in[4];
    float* acc = (float*)d_out;

    const int nnz = in_sizes[2];

    const int THREADS = 256;                              // multiple of 16
    const int total4 = NT * D / 4;                        // 2.4M
    int gridElem = (total4 + THREADS - 1) / THREADS;
    if (gridElem > 148 * 16) gridElem = 148 * 16;

    long long spmmThreads = (long long)nnz * 16;          // 76.8M
    long long gs = (spmmThreads + THREADS - 1) / THREADS;
    int gridSpmm = (gs > 148 * 64) ? 148 * 64 : (int)gs;  // cap; grid-stride covers rest

    lgcn_init<<<gridElem, THREADS>>>(ue, ie, acc);
    for (int l = 0; l < NLAYERS; l++) {
        lgcn_spmm<<<gridSpmm, THREADS>>>(arow, acol, aval, nnz);
        lgcn_combine<<<gridElem, THREADS>>>(acc, (l == NLAYERS - 1) ? 1 : 0);
    }
}

// round 9
// speedup vs baseline: 1.3412x; 1.3412x over previous
#include <cuda_runtime.h>
#include <cstdint>

// Problem constants (fixed by the dataset)
#define NU 100000
#define NI 50000
#define NT (NU + NI)        // 150000 total nodes
#define D  64               // factors
#define D4 (D / 4)          // 16 float4 per row
#define NLAYERS 3
#define NNZ_MAX 4800000

#define SCAN_THREADS 1024
#define SCAN_ITEMS   4
#define SCAN_CHUNK   (SCAN_THREADS * SCAN_ITEMS)          // 4096
#define SCAN_NB      ((NT + SCAN_CHUNK - 1) / SCAN_CHUNK) // 37

// Static device scratch (allocation is forbidden)
__device__ float g_bufA[(size_t)NT * D];   // ping-pong embedding buffers
__device__ float g_bufB[(size_t)NT * D];
__device__ int2  g_csr[NNZ_MAX];           // {col, val_bits} in CSR order
__device__ int   g_cnt[NT];                // per-row degree counts
__device__ int   g_rowptr[NT + 1];         // CSR row pointers
__device__ int   g_fill[NT];               // scatter fill cursors
__device__ int   g_bsum[SCAN_NB];          // scan block sums

// ---------------------------------------------------------------------------
// init: bufA = concat(user_emb, item_emb); acc (=d_out) = bufA;
//       zero g_cnt / g_fill.
// ---------------------------------------------------------------------------
__global__ void lgcn_init(const float* __restrict__ ue,
                          const float* __restrict__ ie,
                          float* __restrict__ acc) {
    int i = blockIdx.x * blockDim.x + threadIdx.x;
    const int total4 = NT * D4;
    const int user4  = NU * D4;
    if (i < total4) {
        float4 v;
        if (i < user4) v = reinterpret_cast<const float4*>(ue)[i];
        else           v = reinterpret_cast<const float4*>(ie)[i - user4];
        reinterpret_cast<float4*>(g_bufA)[i] = v;
        reinterpret_cast<float4*>(acc)[i]    = v;
    }
    if (i < NT) { g_cnt[i] = 0; g_fill[i] = 0; }
}

// ---------------------------------------------------------------------------
// histogram: count in-edges per destination row
// ---------------------------------------------------------------------------
__global__ void lgcn_hist(const int* __restrict__ row, int nnz) {
    int e = blockIdx.x * blockDim.x + threadIdx.x;
    if (e < nnz) atomicAdd(&g_cnt[row[e]], 1);
}

// ---------------------------------------------------------------------------
// exclusive scan of g_cnt[NT] -> g_rowptr (3 small kernels)
// ---------------------------------------------------------------------------
__global__ void lgcn_scan1() {
    __shared__ int sh[SCAN_THREADS];
    int t = threadIdx.x;
    int base = blockIdx.x * SCAN_CHUNK + t * SCAN_ITEMS;
    int v[SCAN_ITEMS];
    int s = 0;
#pragma unroll
    for (int j = 0; j < SCAN_ITEMS; j++) {
        int idx = base + j;
        v[j] = (idx < NT) ? g_cnt[idx] : 0;
        s += v[j];
    }
    sh[t] = s;
    __syncthreads();
    for (int off = 1; off < SCAN_THREADS; off <<= 1) {
        int x = sh[t];
        int y = (t >= off) ? sh[t - off] : 0;
        __syncthreads();
        sh[t] = x + y;
        __syncthreads();
    }
    int excl = sh[t] - s;
#pragma unroll
    for (int j = 0; j < SCAN_ITEMS; j++) {
        int idx = base + j;
        if (idx < NT) g_rowptr[idx] = excl;
        excl += v[j];
    }
    if (t == SCAN_THREADS - 1) g_bsum[blockIdx.x] = sh[SCAN_THREADS - 1];
}

__global__ void lgcn_scan2() {
    if (threadIdx.x == 0) {
        int run = 0;
        for (int b = 0; b < SCAN_NB; b++) {
            int x = g_bsum[b];
            g_bsum[b] = run;
            run += x;
        }
    }
}

__global__ void lgcn_scan3(int nnz) {
    int i = blockIdx.x * blockDim.x + threadIdx.x;
    if (i < NT) g_rowptr[i] += g_bsum[i / SCAN_CHUNK];
    if (i == 0) g_rowptr[NT] = nnz;
}

// ---------------------------------------------------------------------------
// scatter edges into CSR order: g_csr[rowptr[r] + fill[r]++] = {col, val}
// ---------------------------------------------------------------------------
__global__ void lgcn_scatter(const int* __restrict__ row,
                             const int* __restrict__ col,
                             const float* __restrict__ val,
                             int nnz) {
    int e = blockIdx.x * blockDim.x + threadIdx.x;
    if (e >= nnz) return;
    int r = row[e];
    int pos = g_rowptr[r] + atomicAdd(&g_fill[r], 1);
    g_csr[pos] = make_int2(col[e], __float_as_int(val[e]));
}

// ---------------------------------------------------------------------------
// CSR SpMM fused with running-mean update.
//   next[r] = sum_{edges of r} val * cur[col]   (plain store, no atomics)
//   acc[r] += sum      (last layer: acc = (acc + sum) * 0.25)
// 16 lanes per row; each lane owns one float4 of the 64-dim row.
// Edge (col,val) pairs loaded 16-wide and broadcast via shfl (width 16).
// cur/next resolved from __device__ symbols IN DEVICE CODE via flip —
// passing device symbols from host gives the host shadow address (ATS makes
// that silently readable on GB300 -> garbage output, seen in R6).
// ---------------------------------------------------------------------------
__global__ void lgcn_spmm_csr(float* __restrict__ acc, int flip, int last) {
    const float* __restrict__ cur  = flip ? g_bufB : g_bufA;
    float*       __restrict__ next = flip ? g_bufA : g_bufB;

    const unsigned FULL = 0xffffffffu;
    int t   = blockIdx.x * blockDim.x + threadIdx.x;
    int r   = t >> 4;          // row
    int seg = t & 15;          // float4 segment within row
    if (r >= NT) return;

    int start = g_rowptr[r];
    int end   = g_rowptr[r + 1];

    float4 s = make_float4(0.f, 0.f, 0.f, 0.f);
    const float4* cur4 = reinterpret_cast<const float4*>(cur);

    int k = start;
    for (; k + 16 <= end; k += 16) {       // full 16-edge chunks
        int2 cv = __ldg(&g_csr[k + seg]);
#pragma unroll
        for (int j = 0; j < 16; j++) {
            int   c = __shfl_sync(FULL, cv.x, j, 16);
            float v = __int_as_float(__shfl_sync(FULL, cv.y, j, 16));
            float4 x = __ldg(cur4 + (size_t)c * D4 + seg);
            s.x += v * x.x; s.y += v * x.y; s.z += v * x.z; s.w += v * x.w;
        }
    }
    if (k < end) {                          // tail (1..15 edges)
        int lim = end - k;
        int idx = k + seg;
        int2 cv = (idx < end) ? __ldg(&g_csr[idx]) : make_int2(0, 0);
        for (int j = 0; j < lim; j++) {
            int   c = __shfl_sync(FULL, cv.x, j, 16);
            float v = __int_as_float(__shfl_sync(FULL, cv.y, j, 16));
            float4 x = __ldg(cur4 + (size_t)c * D4 + seg);
            s.x += v * x.x; s.y += v * x.y; s.z += v * x.z; s.w += v * x.w;
        }
    }

    size_t o = (size_t)r * D4 + seg;
    reinterpret_cast<float4*>(next)[o] = s;

    float4 a = reinterpret_cast<float4*>(acc)[o];
    a.x += s.x; a.y += s.y; a.z += s.z; a.w += s.w;
    if (last) { a.x *= 0.25f; a.y *= 0.25f; a.z *= 0.25f; a.w *= 0.25f; }
    reinterpret_cast<float4*>(acc)[o] = a;
}

// ---------------------------------------------------------------------------
// launch
// Inputs (metadata order): user_emb f32 [NU*D], item_emb f32 [NI*D],
//                          adj_row i32 [NNZ], adj_col i32 [NNZ], adj_val f32 [NNZ]
// Output: mean_emb f32 [NT*D] (users then items)
// ---------------------------------------------------------------------------
extern "C" void kernel_launch(void* const* d_in, const int* in_sizes, int n_in,
                              void* d_out, int out_size) {
    const float* ue   = (const float*)d_in[0];
    const float* ie   = (const float*)d_in[1];
    const int*   arow = (const int*)d_in[2];
    const int*   acol = (const int*)d_in[3];
    const float* aval = (const float*)d_in[4];
    float* acc = (float*)d_out;

    int nnz = in_sizes[2];
    if (nnz > NNZ_MAX) nnz = NNZ_MAX;   // static scratch bound (dataset-fixed)

    const int THREADS = 256;
    const int total4   = NT * D4;                           // 2.4M
    const int gridInit = (total4 + THREADS - 1) / THREADS;  // also covers NT
    const int gridEdge = (nnz + THREADS - 1) / THREADS;
    const int gridRowP = (NT + THREADS - 1) / THREADS;
    const int gridSpmm = (NT * 16 + THREADS - 1) / THREADS;

    // build initial embeddings + CSR (once per launch/replay)
    lgcn_init<<<gridInit, THREADS>>>(ue, ie, acc);
    lgcn_hist<<<gridEdge, THREADS>>>(arow, nnz);
    lgcn_scan1<<<SCAN_NB, SCAN_THREADS>>>();
    lgcn_scan2<<<1, 32>>>();
    lgcn_scan3<<<gridRowP, THREADS>>>(nnz);
    lgcn_scatter<<<gridEdge, THREADS>>>(arow, acol, aval, nnz);

    // 3 propagation layers; cur/next resolved inside the kernel via flip
    for (int l = 0; l < NLAYERS; l++) {
        int last = (l == NLAYERS - 1) ? 1 : 0;
        lgcn_spmm_csr<<<gridSpmm, THREADS>>>(acc, l & 1, last);
    }
}